// round 6
// baseline (speedup 1.0000x reference)
#include <cuda_runtime.h>
#include <math.h>

#define S 8192
#define D 2048
#define WSTRIDE 4096           // W row stride (2*D)
#define NCTA_REC 128
#define ROWS_PER_CTA 16        // D / NCTA_REC
#define NCHUNK 64
#define CHUNK 128              // S / NCHUNK
#define REC_THREADS 512
#define NREP 32                // counter replicas (one L2 line each, 32KB stride)

typedef unsigned long long ull;

// ---- scratch (no runtime allocation allowed) ----
__device__ float g_hc[(size_t)S * D];        // cummax result
__device__ float g_cp[(size_t)S * D];        // ctx_proj result
__device__ float g_chunkmax[NCHUNK * D];     // cummax phase-B scratch
__device__ int   g_rep[NREP * S];            // replicated per-step counters

#define NEG_INF __int_as_float(0xff800000)

// ---- packed f32x2 helpers ----
__device__ __forceinline__ ull ffma2(ull a, ull b, ull c) {
    ull d;
    asm("fma.rn.f32x2 %0, %1, %2, %3;" : "=l"(d) : "l"(a), "l"(b), "l"(c));
    return d;
}
__device__ __forceinline__ ull pack2(unsigned int lo, unsigned int hi) {
    ull v;
    asm("mov.b64 %0, {%1, %2};" : "=l"(v) : "r"(lo), "r"(hi));
    return v;
}
__device__ __forceinline__ ull pack2f(float x, float y) {
    ull v;
    asm("mov.b64 %0, {%1, %2};" : "=l"(v) : "f"(x), "f"(y));
    return v;
}
__device__ __forceinline__ ull dup2f(float x) {
    ull v;
    asm("mov.b64 %0, {%1, %1};" : "=l"(v) : "f"(x));
    return v;
}
__device__ __forceinline__ float2 unpack2(ull v) {
    float2 r;
    asm("mov.b64 {%0, %1}, %2;" : "=f"(r.x), "=f"(r.y) : "l"(v));
    return r;
}

// ---- fence-free acquire/release primitives ----
__device__ __forceinline__ int ld_acquire_gpu(const int* p) {
    int v;
    asm volatile("ld.acquire.gpu.global.s32 %0, [%1];" : "=r"(v) : "l"(p) : "memory");
    return v;
}
__device__ __forceinline__ void red_release_gpu_add(int* p, int v) {
    asm volatile("red.release.gpu.global.add.s32 [%0], %1;" :: "l"(p), "r"(v) : "memory");
}

// ============================================================
// counter reset (graph replays must start from zeroed counters)
// ============================================================
__global__ void zero_flags_kernel() {
    int idx = blockIdx.x * blockDim.x + threadIdx.x;
    if (idx < NREP * S) g_rep[idx] = 0;
}

// ============================================================
// cummax phase A: per-(chunk, col) max
// ============================================================
__global__ void cummax_chunk_kernel(const float* __restrict__ ce) {
    int col = blockIdx.x * blockDim.x + threadIdx.x;
    int chunk = blockIdx.y;
    const float* p = ce + (size_t)chunk * CHUNK * D + col;
    float m = NEG_INF;
#pragma unroll 8
    for (int r = 0; r < CHUNK; r++) {
        m = fmaxf(m, p[(size_t)r * D]);
    }
    g_chunkmax[chunk * D + col] = m;
}

// ============================================================
// cummax phase B: exclusive prefix-max over chunks, per column
// ============================================================
__global__ void cummax_scan_kernel() {
    int col = blockIdx.x * blockDim.x + threadIdx.x;
    float run = NEG_INF;
    for (int ch = 0; ch < NCHUNK; ch++) {
        float v = g_chunkmax[ch * D + col];
        g_chunkmax[ch * D + col] = run;   // exclusive prefix
        run = fmaxf(run, v);
    }
}

// ============================================================
// cummax phase C: inclusive scan within chunk seeded by prefix
// ============================================================
__global__ void cummax_write_kernel(const float* __restrict__ ce) {
    int col = blockIdx.x * blockDim.x + threadIdx.x;
    int chunk = blockIdx.y;
    float m = g_chunkmax[chunk * D + col];
    const float* p = ce + (size_t)chunk * CHUNK * D + col;
    float*       q = g_hc + (size_t)chunk * CHUNK * D + col;
#pragma unroll 8
    for (int r = 0; r < CHUNK; r++) {
        m = fmaxf(m, p[(size_t)r * D]);
        q[(size_t)r * D] = m;
    }
}

// ============================================================
// GEMM: g_cp[t][i] = sum_j ce[t][j] * W[i][D + j] + b[i]
// f32x2 packed FFMA: accumulators are (n, n+1) pairs.
// ============================================================
#define GT 128
#define GI 128
#define GK 8
#define GPAD 4

__global__ __launch_bounds__(256) void gemm_ctx_kernel(
    const float* __restrict__ A,
    const float* __restrict__ W,
    const float* __restrict__ bias)
{
    __shared__ float As[GK][GT + GPAD];
    __shared__ float Bs[GK][GI + GPAD];

    int tid = threadIdx.x;
    int tx = tid & 15;
    int ty = tid >> 4;
    int i0 = blockIdx.x * GI;
    int t0 = blockIdx.y * GT;

    int lr = tid >> 1;
    int lk = (tid & 1) * 4;

    const float* Ap = A + (size_t)(t0 + lr) * D + lk;
    const float* Bp = W + (size_t)(i0 + lr) * WSTRIDE + D + lk;

    ull acc[8][4];
#pragma unroll
    for (int m = 0; m < 8; m++)
#pragma unroll
        for (int n = 0; n < 4; n++) acc[m][n] = 0ULL;

    float4 ra = *(const float4*)Ap;
    float4 rb = *(const float4*)Bp;

    for (int kk = 0; kk < D; kk += GK) {
        As[lk + 0][lr] = ra.x; As[lk + 1][lr] = ra.y;
        As[lk + 2][lr] = ra.z; As[lk + 3][lr] = ra.w;
        Bs[lk + 0][lr] = rb.x; Bs[lk + 1][lr] = rb.y;
        Bs[lk + 2][lr] = rb.z; Bs[lk + 3][lr] = rb.w;
        __syncthreads();

        if (kk + GK < D) {
            ra = *(const float4*)(Ap + kk + GK);
            rb = *(const float4*)(Bp + kk + GK);
        }

#pragma unroll
        for (int k = 0; k < GK; k++) {
            float4 a0 = *(const float4*)&As[k][ty * 8];
            float4 a1 = *(const float4*)&As[k][ty * 8 + 4];
            float4 b0 = *(const float4*)&Bs[k][tx * 8];
            float4 b1 = *(const float4*)&Bs[k][tx * 8 + 4];
            ull bp[4] = {pack2f(b0.x, b0.y), pack2f(b0.z, b0.w),
                         pack2f(b1.x, b1.y), pack2f(b1.z, b1.w)};
            ull ad[8] = {dup2f(a0.x), dup2f(a0.y), dup2f(a0.z), dup2f(a0.w),
                         dup2f(a1.x), dup2f(a1.y), dup2f(a1.z), dup2f(a1.w)};
#pragma unroll
            for (int m = 0; m < 8; m++)
#pragma unroll
                for (int n = 0; n < 4; n++)
                    acc[m][n] = ffma2(ad[m], bp[n], acc[m][n]);
        }
        __syncthreads();
    }

    float bv[8];
#pragma unroll
    for (int n = 0; n < 8; n++) bv[n] = bias[i0 + tx * 8 + n];

#pragma unroll
    for (int m = 0; m < 8; m++) {
        size_t row = (size_t)(t0 + ty * 8 + m) * D + i0 + tx * 8;
        float2 c0 = unpack2(acc[m][0]), c1 = unpack2(acc[m][1]);
        float2 c2 = unpack2(acc[m][2]), c3 = unpack2(acc[m][3]);
        float4 o0 = make_float4(c0.x + bv[0], c0.y + bv[1],
                                c1.x + bv[2], c1.y + bv[3]);
        float4 o1 = make_float4(c2.x + bv[4], c2.y + bv[5],
                                c3.x + bv[6], c3.y + bv[7]);
        *(float4*)&g_cp[row]     = o0;
        *(float4*)&g_cp[row + 4] = o1;
    }
}

// ============================================================
// Recurrence v5: 128 CTAs x 512 threads (16 warps), replicated-counter sync.
// Warp w owns output row i0+w; lane covers 4 x 16-col groups. W in regs.
// Publish: warp 0 release-REDs +1 to ALL 32 replicas (spread addresses).
// Wait:   tid 0 acquire-polls replica (cta & 31) only -> 4 pollers/line.
// ============================================================
__global__ __launch_bounds__(REC_THREADS, 1) void recurrence_kernel(
    const float* __restrict__ W,
    float* out)
{
    int tid  = threadIdx.x;
    int lane = tid & 31;
    int w    = tid >> 5;          // warp = row within CTA slice
    int cta  = blockIdx.x;
    int row  = cta * ROWS_PER_CTA + w;
    const int myrep = (cta & (NREP - 1)) * S;   // this CTA's poll replica base

    // ---- preload W row slice: 4 chunks x 16 cols, as f32x2 pairs ----
    ull wreg[32];
    {
        const float* wp = W + (size_t)row * WSTRIDE;
#pragma unroll
        for (int j = 0; j < 4; j++) {
            const float* p = wp + j * 512 + lane * 16;
#pragma unroll
            for (int q = 0; q < 4; q++) {
                uint4 v = *(const uint4*)(p + q * 4);
                wreg[j * 8 + q * 2 + 0] = pack2(v.x, v.y);
                wreg[j * 8 + q * 2 + 1] = pack2(v.z, v.w);
            }
        }
    }

    const ull m1 = dup2f(-1.0f);

    for (int t = 0; t < S; t++) {
        // per-row hc/cp prefetch (in flight during poll/bar)
        float hcv = 0.0f, cpv = 0.0f;
        if (lane == 0) {
            hcv = __ldg(&g_hc[(size_t)t * D + row]);
            cpv = __ldg(&g_cp[(size_t)t * D + row]);
        }

        // ---- wait for row t-1 on this CTA's private replica line ----
        if (t > 0 && tid == 0) {
            while (ld_acquire_gpu(&g_rep[myrep + t - 1]) < NCTA_REC) { }
        }
        __syncthreads();

        // ---- partial dot: 64 cols/lane, packed f32x2 ----
        ull a0 = 0, a1 = 0, a2 = 0, a3 = 0;
        if (t == 0) {
#pragma unroll
            for (int j = 0; j < 8; j++) {
                a0 = ffma2(wreg[j * 4 + 0], m1, a0);
                a1 = ffma2(wreg[j * 4 + 1], m1, a1);
                a2 = ffma2(wreg[j * 4 + 2], m1, a2);
                a3 = ffma2(wreg[j * 4 + 3], m1, a3);
            }
        } else {
            const float* src = out + (size_t)(t - 1) * D;
#pragma unroll
            for (int j = 0; j < 4; j++) {
                const float* p = src + j * 512 + lane * 16;
                uint4 v0 = *(const uint4*)(p + 0);
                uint4 v1 = *(const uint4*)(p + 4);
                uint4 v2 = *(const uint4*)(p + 8);
                uint4 v3 = *(const uint4*)(p + 12);
                a0 = ffma2(wreg[j * 8 + 0], pack2(v0.x, v0.y), a0);
                a1 = ffma2(wreg[j * 8 + 1], pack2(v0.z, v0.w), a1);
                a2 = ffma2(wreg[j * 8 + 2], pack2(v1.x, v1.y), a2);
                a3 = ffma2(wreg[j * 8 + 3], pack2(v1.z, v1.w), a3);
                a0 = ffma2(wreg[j * 8 + 4], pack2(v2.x, v2.y), a0);
                a1 = ffma2(wreg[j * 8 + 5], pack2(v2.z, v2.w), a1);
                a2 = ffma2(wreg[j * 8 + 6], pack2(v3.x, v3.y), a2);
                a3 = ffma2(wreg[j * 8 + 7], pack2(v3.z, v3.w), a3);
            }
        }
        float2 f0 = unpack2(a0), f1 = unpack2(a1),
               f2 = unpack2(a2), f3 = unpack2(a3);
        float r = (f0.x + f0.y) + (f1.x + f1.y)
                + (f2.x + f2.y) + (f3.x + f3.y);

        // ---- intra-warp reduction: full row sum ----
#pragma unroll
        for (int off = 16; off > 0; off >>= 1)
            r += __shfl_xor_sync(0xFFFFFFFFu, r, off);

        // ---- lane 0 finalizes its row ----
        if (lane == 0) {
            float x  = r + cpv;
            float g  = 1.0f / (1.0f + __expf(-x));
            float ns = hcv * g;
            __stcg(&out[(size_t)t * D + row], ns);
            if (t == S - 1) __stcg(&out[(size_t)S * D + row], ns);
        }
        __syncthreads();   // all 16 rows stored before the CTA's release

        // ---- publish step t to all replicas (warp 0, spread addresses) ----
        if (tid < NREP)
            red_release_gpu_add(&g_rep[tid * S + t], 1);
    }
}

// ============================================================
extern "C" void kernel_launch(void* const* d_in, const int* in_sizes, int n_in,
                              void* d_out, int out_size) {
    const float* ce = (const float*)d_in[0];   // (S, D)
    const float* W  = (const float*)d_in[1];   // (D, 2D)
    const float* b  = (const float*)d_in[2];   // (D,)
    float* out = (float*)d_out;                // (S*D + D) floats

    zero_flags_kernel<<<(NREP * S + 1023) / 1024, 1024>>>();

    dim3 cgrid(D / 256, NCHUNK);
    cummax_chunk_kernel<<<cgrid, 256>>>(ce);
    cummax_scan_kernel<<<D / 256, 256>>>();
    cummax_write_kernel<<<cgrid, 256>>>(ce);

    dim3 ggrid(D / GI, S / GT);
    gemm_ctx_kernel<<<ggrid, 256>>>(ce, W, b);

    recurrence_kernel<<<NCTA_REC, REC_THREADS>>>(W, out);
}

// round 7
// speedup vs baseline: 1.1935x; 1.1935x over previous
#include <cuda_runtime.h>
#include <math.h>

#define S 8192
#define D 2048
#define WSTRIDE 4096           // W row stride (2*D)
#define NCTA_REC 128
#define ROWS_PER_CTA 16        // D / NCTA_REC
#define NCHUNK 64
#define CHUNK 128              // S / NCHUNK
#define REC_THREADS 512

typedef unsigned long long ull;

// ---- scratch (no runtime allocation allowed) ----
__device__ float g_hc[(size_t)S * D];        // cummax result
__device__ float g_cp[(size_t)S * D];        // ctx_proj result
__device__ float g_chunkmax[NCHUNK * D];     // cummax phase-B scratch
__device__ int   g_flagv[NCTA_REC];          // per-CTA monotonic step counters

#define NEG_INF __int_as_float(0xff800000)

// ---- packed f32x2 helpers ----
__device__ __forceinline__ ull ffma2(ull a, ull b, ull c) {
    ull d;
    asm("fma.rn.f32x2 %0, %1, %2, %3;" : "=l"(d) : "l"(a), "l"(b), "l"(c));
    return d;
}
__device__ __forceinline__ ull pack2(unsigned int lo, unsigned int hi) {
    ull v;
    asm("mov.b64 %0, {%1, %2};" : "=l"(v) : "r"(lo), "r"(hi));
    return v;
}
__device__ __forceinline__ ull pack2f(float x, float y) {
    ull v;
    asm("mov.b64 %0, {%1, %2};" : "=l"(v) : "f"(x), "f"(y));
    return v;
}
__device__ __forceinline__ ull dup2f(float x) {
    ull v;
    asm("mov.b64 %0, {%1, %1};" : "=l"(v) : "f"(x));
    return v;
}
__device__ __forceinline__ float2 unpack2(ull v) {
    float2 r;
    asm("mov.b64 {%0, %1}, %2;" : "=f"(r.x), "=f"(r.y) : "l"(v));
    return r;
}

// ---- fence-free acquire/release primitives (NO atomics) ----
__device__ __forceinline__ int ld_acquire_gpu(const int* p) {
    int v;
    asm volatile("ld.acquire.gpu.global.s32 %0, [%1];" : "=r"(v) : "l"(p) : "memory");
    return v;
}
__device__ __forceinline__ void st_release_gpu(int* p, int v) {
    asm volatile("st.release.gpu.global.s32 [%0], %1;" :: "l"(p), "r"(v) : "memory");
}

// ============================================================
// flag reset (graph replays must start from zeroed counters)
// ============================================================
__global__ void zero_flags_kernel() {
    int idx = threadIdx.x;
    if (idx < NCTA_REC) g_flagv[idx] = 0;
}

// ============================================================
// cummax phase A: per-(chunk, col) max
// ============================================================
__global__ void cummax_chunk_kernel(const float* __restrict__ ce) {
    int col = blockIdx.x * blockDim.x + threadIdx.x;
    int chunk = blockIdx.y;
    const float* p = ce + (size_t)chunk * CHUNK * D + col;
    float m = NEG_INF;
#pragma unroll 8
    for (int r = 0; r < CHUNK; r++) {
        m = fmaxf(m, p[(size_t)r * D]);
    }
    g_chunkmax[chunk * D + col] = m;
}

// ============================================================
// cummax phase B: exclusive prefix-max over chunks, per column
// ============================================================
__global__ void cummax_scan_kernel() {
    int col = blockIdx.x * blockDim.x + threadIdx.x;
    float run = NEG_INF;
    for (int ch = 0; ch < NCHUNK; ch++) {
        float v = g_chunkmax[ch * D + col];
        g_chunkmax[ch * D + col] = run;   // exclusive prefix
        run = fmaxf(run, v);
    }
}

// ============================================================
// cummax phase C: inclusive scan within chunk seeded by prefix
// ============================================================
__global__ void cummax_write_kernel(const float* __restrict__ ce) {
    int col = blockIdx.x * blockDim.x + threadIdx.x;
    int chunk = blockIdx.y;
    float m = g_chunkmax[chunk * D + col];
    const float* p = ce + (size_t)chunk * CHUNK * D + col;
    float*       q = g_hc + (size_t)chunk * CHUNK * D + col;
#pragma unroll 8
    for (int r = 0; r < CHUNK; r++) {
        m = fmaxf(m, p[(size_t)r * D]);
        q[(size_t)r * D] = m;
    }
}

// ============================================================
// GEMM: g_cp[t][i] = sum_j ce[t][j] * W[i][D + j] + b[i]
// f32x2 packed FFMA.
// ============================================================
#define GT 128
#define GI 128
#define GK 8
#define GPAD 4

__global__ __launch_bounds__(256) void gemm_ctx_kernel(
    const float* __restrict__ A,
    const float* __restrict__ W,
    const float* __restrict__ bias)
{
    __shared__ float As[GK][GT + GPAD];
    __shared__ float Bs[GK][GI + GPAD];

    int tid = threadIdx.x;
    int tx = tid & 15;
    int ty = tid >> 4;
    int i0 = blockIdx.x * GI;
    int t0 = blockIdx.y * GT;

    int lr = tid >> 1;
    int lk = (tid & 1) * 4;

    const float* Ap = A + (size_t)(t0 + lr) * D + lk;
    const float* Bp = W + (size_t)(i0 + lr) * WSTRIDE + D + lk;

    ull acc[8][4];
#pragma unroll
    for (int m = 0; m < 8; m++)
#pragma unroll
        for (int n = 0; n < 4; n++) acc[m][n] = 0ULL;

    float4 ra = *(const float4*)Ap;
    float4 rb = *(const float4*)Bp;

    for (int kk = 0; kk < D; kk += GK) {
        As[lk + 0][lr] = ra.x; As[lk + 1][lr] = ra.y;
        As[lk + 2][lr] = ra.z; As[lk + 3][lr] = ra.w;
        Bs[lk + 0][lr] = rb.x; Bs[lk + 1][lr] = rb.y;
        Bs[lk + 2][lr] = rb.z; Bs[lk + 3][lr] = rb.w;
        __syncthreads();

        if (kk + GK < D) {
            ra = *(const float4*)(Ap + kk + GK);
            rb = *(const float4*)(Bp + kk + GK);
        }

#pragma unroll
        for (int k = 0; k < GK; k++) {
            float4 a0 = *(const float4*)&As[k][ty * 8];
            float4 a1 = *(const float4*)&As[k][ty * 8 + 4];
            float4 b0 = *(const float4*)&Bs[k][tx * 8];
            float4 b1 = *(const float4*)&Bs[k][tx * 8 + 4];
            ull bp[4] = {pack2f(b0.x, b0.y), pack2f(b0.z, b0.w),
                         pack2f(b1.x, b1.y), pack2f(b1.z, b1.w)};
            ull ad[8] = {dup2f(a0.x), dup2f(a0.y), dup2f(a0.z), dup2f(a0.w),
                         dup2f(a1.x), dup2f(a1.y), dup2f(a1.z), dup2f(a1.w)};
#pragma unroll
            for (int m = 0; m < 8; m++)
#pragma unroll
                for (int n = 0; n < 4; n++)
                    acc[m][n] = ffma2(ad[m], bp[n], acc[m][n]);
        }
        __syncthreads();
    }

    float bv[8];
#pragma unroll
    for (int n = 0; n < 8; n++) bv[n] = bias[i0 + tx * 8 + n];

#pragma unroll
    for (int m = 0; m < 8; m++) {
        size_t row = (size_t)(t0 + ty * 8 + m) * D + i0 + tx * 8;
        float2 c0 = unpack2(acc[m][0]), c1 = unpack2(acc[m][1]);
        float2 c2 = unpack2(acc[m][2]), c3 = unpack2(acc[m][3]);
        float4 o0 = make_float4(c0.x + bv[0], c0.y + bv[1],
                                c1.x + bv[2], c1.y + bv[3]);
        float4 o1 = make_float4(c2.x + bv[4], c2.y + bv[5],
                                c3.x + bv[6], c3.y + bv[7]);
        *(float4*)&g_cp[row]     = o0;
        *(float4*)&g_cp[row + 4] = o1;
    }
}

// ============================================================
// Recurrence v6: 128 CTAs x 512 threads. NO atomics in the sync.
// Layout (proven in v3): c = tid & 127 owns 16 state cols, rgrp = tid >> 7
// owns 4 rows. W slice in regs (f32x2). State via plain cached loads
// (lines are fresh per step and only touched after publication -> L1 safe;
// 4-way dup hits L1, L2 traffic 1MB/step).
// Publish: one st.release.gpu per CTA to its own flag (distinct addresses,
// zero LTS atomic serialization). Wait: warp 0 polls all 128 flags with
// warp-wide ld.acquire (4 per lane), __all_sync, then __syncthreads.
// ============================================================
__global__ __launch_bounds__(REC_THREADS, 1) void recurrence_kernel(
    const float* __restrict__ W,
    float* out)
{
    __shared__ float s_red[2][16 * 4];   // [buf][row*4 + colpart]

    int tid  = threadIdx.x;
    int lane = tid & 31;
    int wrp  = tid >> 5;          // 0..15
    int c    = tid & 127;         // column segment
    int rgrp = tid >> 7;          // 0..3
    int wq   = wrp & 3;           // colpart within reduction
    int cta  = blockIdx.x;
    int i0   = cta * ROWS_PER_CTA;

    // ---- preload W slice as f32x2 pairs ----
    ull w2[4][8];
#pragma unroll
    for (int m = 0; m < 4; m++) {
        const float* wp = W + (size_t)(i0 + rgrp * 4 + m) * WSTRIDE + c * 16;
#pragma unroll
        for (int j = 0; j < 4; j++) {
            uint4 q = *(const uint4*)(wp + j * 4);
            w2[m][j * 2 + 0] = pack2(q.x, q.y);
            w2[m][j * 2 + 1] = pack2(q.z, q.w);
        }
    }

    const ull minus1 = pack2(__float_as_uint(-1.0f), __float_as_uint(-1.0f));

    for (int t = 0; t < S; t++) {
        // prefetch hc/cp for finalize lanes (in flight during poll)
        float hcv = 0.0f, cpv = 0.0f;
        if (tid < ROWS_PER_CTA) {
            hcv = __ldg(&g_hc[(size_t)t * D + i0 + tid]);
            cpv = __ldg(&g_cp[(size_t)t * D + i0 + tid]);
        }

        // ---- wait until ALL 128 CTAs have published row t-1 ----
        if (t > 0 && wrp == 0) {
            const int* fp = g_flagv + lane;
            for (;;) {
                int f0 = ld_acquire_gpu(fp);
                int f1 = ld_acquire_gpu(fp + 32);
                int f2 = ld_acquire_gpu(fp + 64);
                int f3 = ld_acquire_gpu(fp + 96);
                int mn = min(min(f0, f1), min(f2, f3));
                if (__all_sync(0xFFFFFFFFu, mn >= t)) break;
            }
        }
        __syncthreads();

        // ---- obtain state segment (plain cached loads) ----
        ull sp[8];
        if (t == 0) {
#pragma unroll
            for (int j = 0; j < 8; j++) sp[j] = minus1;
        } else {
            const float* src = out + (size_t)(t - 1) * D + c * 16;
#pragma unroll
            for (int j = 0; j < 4; j++) {
                uint4 q = *(const uint4*)(src + j * 4);
                sp[j * 2 + 0] = pack2(q.x, q.y);
                sp[j * 2 + 1] = pack2(q.z, q.w);
            }
        }

        // ---- 4-row x 16-col partial matvec, packed f32x2 ----
        ull a0 = 0, a1 = 0, a2 = 0, a3 = 0;
#pragma unroll
        for (int j = 0; j < 8; j++) {
            a0 = ffma2(w2[0][j], sp[j], a0);
            a1 = ffma2(w2[1][j], sp[j], a1);
            a2 = ffma2(w2[2][j], sp[j], a2);
            a3 = ffma2(w2[3][j], sp[j], a3);
        }
        float2 f0 = unpack2(a0), f1 = unpack2(a1),
               f2 = unpack2(a2), f3 = unpack2(a3);
        float r0 = f0.x + f0.y;
        float r1 = f1.x + f1.y;
        float r2 = f2.x + f2.y;
        float r3 = f3.x + f3.y;

        // ---- warp shuffle reduction over 32 column segments ----
#pragma unroll
        for (int off = 16; off > 0; off >>= 1) {
            r0 += __shfl_xor_sync(0xFFFFFFFFu, r0, off);
            r1 += __shfl_xor_sync(0xFFFFFFFFu, r1, off);
            r2 += __shfl_xor_sync(0xFFFFFFFFu, r2, off);
            r3 += __shfl_xor_sync(0xFFFFFFFFu, r3, off);
        }
        int buf = t & 1;
        if (lane == 0) {
            int rb = rgrp * 4;
            s_red[buf][(rb + 0) * 4 + wq] = r0;
            s_red[buf][(rb + 1) * 4 + wq] = r1;
            s_red[buf][(rb + 2) * 4 + wq] = r2;
            s_red[buf][(rb + 3) * 4 + wq] = r3;
        }
        __syncthreads();

        // ---- finalize: 16 lanes of warp 0, then release-store the flag ----
        if (tid < ROWS_PER_CTA) {
            float s = s_red[buf][tid * 4 + 0] + s_red[buf][tid * 4 + 1]
                    + s_red[buf][tid * 4 + 2] + s_red[buf][tid * 4 + 3];
            float x  = s + cpv;
            float g  = 1.0f / (1.0f + __expf(-x));
            float ns = hcv * g;
            __stcg(&out[(size_t)t * D + i0 + tid], ns);
            if (t == S - 1) __stcg(&out[(size_t)S * D + i0 + tid], ns);
            __syncwarp(0x0000FFFFu);   // all 16 row stores done
            if (tid == 0)
                st_release_gpu(&g_flagv[cta], t + 1);   // publish step t
        }
        // s_red reuse at t+1 is safe: writes at t+1 occur after the t+1
        // top-of-loop __syncthreads, which follows every reader's access.
    }
}

// ============================================================
extern "C" void kernel_launch(void* const* d_in, const int* in_sizes, int n_in,
                              void* d_out, int out_size) {
    const float* ce = (const float*)d_in[0];   // (S, D)
    const float* W  = (const float*)d_in[1];   // (D, 2D)
    const float* b  = (const float*)d_in[2];   // (D,)
    float* out = (float*)d_out;                // (S*D + D) floats

    zero_flags_kernel<<<1, 128>>>();

    dim3 cgrid(D / 256, NCHUNK);
    cummax_chunk_kernel<<<cgrid, 256>>>(ce);
    cummax_scan_kernel<<<D / 256, 256>>>();
    cummax_write_kernel<<<cgrid, 256>>>(ce);

    dim3 ggrid(D / GI, S / GT);
    gemm_ctx_kernel<<<ggrid, 256>>>(ce, W, b);

    recurrence_kernel<<<NCTA_REC, REC_THREADS>>>(W, out);
}